// round 1
// baseline (speedup 1.0000x reference)
#include <cuda_runtime.h>
#include <math.h>

#define Tn 2048
#define Hn 2048
#define Fn 512
#define En 64
#define Kn 8
#define Cn 320
#define F2n 1024
#define KTn (Kn*Tn)
#define NCHUNK 64
#define CHSZ 256

// ---------------- scratch (device globals; zero-initialized at load) ----------------
__device__ float g_logits[Tn*En];
__device__ int   g_topi[KTn];       // [k*T + t]
__device__ float g_topv[KTn];
__device__ float g_probsum[En];
__device__ int   g_chunkcnt[NCHUNK*En];
__device__ int   g_basecnt[NCHUNK*En];
__device__ int   g_cnt[En];         // capped counts (<= Cn)
__device__ int   g_totcnt[En];      // uncapped (for aux loss)
__device__ int   g_tok[En*Cn];
__device__ float g_wslot[En*Cn];
__device__ float g_hbuf[(size_t)En*Cn*Fn];   // 42 MB, relu(g)*u*w per expert slot
__device__ float g_hs[(size_t)Tn*2*F2n];     // 16 MB, shared-expert hidden

// ---------------- GEMM cores: BM=BN=64, BK=16, 256 threads, 4x4 per thread ----------
__device__ __forceinline__ void gemm1_core(
    const float* const* __restrict__ Arows,
    const float* __restrict__ B, int ldB, int Kd, int n0,
    float acc[16], float* As, float* Bs)
{
    int tid = threadIdx.x;
    int tx = tid & 15, ty = tid >> 4;
    int lmA = tid >> 2, lkA = (tid & 3) << 2;
    int lkB = tid >> 4, lnB = (tid & 15) << 2;
    const float* Bp = B + (size_t)lkB * ldB + n0 + lnB;
    for (int k0 = 0; k0 < Kd; k0 += 16) {
        float4 av = *(const float4*)(Arows[lmA] + k0 + lkA);
        float4 bv = *(const float4*)(Bp);
        Bp += (size_t)16 * ldB;
        *(float4*)(As + lmA*16 + lkA) = av;
        *(float4*)(Bs + lkB*64 + lnB) = bv;
        __syncthreads();
#pragma unroll
        for (int kk = 0; kk < 16; kk++) {
            float4 b = *(const float4*)(Bs + kk*64 + (tx<<2));
#pragma unroll
            for (int i = 0; i < 4; i++) {
                float a = As[(ty*4+i)*16 + kk];
                acc[i*4+0] += a*b.x; acc[i*4+1] += a*b.y;
                acc[i*4+2] += a*b.z; acc[i*4+3] += a*b.w;
            }
        }
        __syncthreads();
    }
}

__device__ __forceinline__ void gemm2_core(
    const float* const* __restrict__ Arows,
    const float* __restrict__ Bg, const float* __restrict__ Bu,
    int ldB, int Kd, int n0,
    float accg[16], float accu[16], float* As, float* Bgs, float* Bus)
{
    int tid = threadIdx.x;
    int tx = tid & 15, ty = tid >> 4;
    int lmA = tid >> 2, lkA = (tid & 3) << 2;
    int lkB = tid >> 4, lnB = (tid & 15) << 2;
    const float* Bgp = Bg + (size_t)lkB * ldB + n0 + lnB;
    const float* Bup = Bu + (size_t)lkB * ldB + n0 + lnB;
    for (int k0 = 0; k0 < Kd; k0 += 16) {
        float4 av  = *(const float4*)(Arows[lmA] + k0 + lkA);
        float4 bgv = *(const float4*)(Bgp);
        float4 buv = *(const float4*)(Bup);
        Bgp += (size_t)16 * ldB;
        Bup += (size_t)16 * ldB;
        *(float4*)(As  + lmA*16 + lkA) = av;
        *(float4*)(Bgs + lkB*64 + lnB) = bgv;
        *(float4*)(Bus + lkB*64 + lnB) = buv;
        __syncthreads();
#pragma unroll
        for (int kk = 0; kk < 16; kk++) {
            float4 bg = *(const float4*)(Bgs + kk*64 + (tx<<2));
            float4 bu = *(const float4*)(Bus + kk*64 + (tx<<2));
#pragma unroll
            for (int i = 0; i < 4; i++) {
                float a = As[(ty*4+i)*16 + kk];
                accg[i*4+0] += a*bg.x; accg[i*4+1] += a*bg.y;
                accg[i*4+2] += a*bg.z; accg[i*4+3] += a*bg.w;
                accu[i*4+0] += a*bu.x; accu[i*4+1] += a*bu.y;
                accu[i*4+2] += a*bu.z; accu[i*4+3] += a*bu.w;
            }
        }
        __syncthreads();
    }
}

// ---------------- small kernels ----------------
__global__ void zero_kernel() {
    if (threadIdx.x < En) g_probsum[threadIdx.x] = 0.f;
}

// logits = x @ router_w : M=T, N=E(=64), K=H
__global__ __launch_bounds__(256) void logits_kernel(
    const float* __restrict__ x, const float* __restrict__ rw)
{
    __shared__ float As[64*16];
    __shared__ float Bs[16*64];
    __shared__ const float* Arows[64];
    int tid = threadIdx.x;
    int m0 = blockIdx.y * 64, n0 = blockIdx.x * 64;
    if (tid < 64) Arows[tid] = x + (size_t)(m0 + tid) * Hn;
    __syncthreads();
    float acc[16] = {};
    gemm1_core(Arows, rw, En, Hn, n0, acc, As, Bs);
    int tx = tid & 15, ty = tid >> 4;
#pragma unroll
    for (int i = 0; i < 4; i++) {
        float4 r = make_float4(acc[i*4+0], acc[i*4+1], acc[i*4+2], acc[i*4+3]);
        *(float4*)(g_logits + (size_t)(m0 + ty*4 + i)*En + n0 + (tx<<2)) = r;
    }
}

// per-token softmax + top-8 + probsum accumulation
__global__ void router_post_kernel() {
    int t = blockIdx.x, tid = threadIdx.x;   // 64 threads
    __shared__ float sp[En];
    __shared__ float red[En];
    float l = g_logits[t*En + tid];
    red[tid] = l; __syncthreads();
    for (int s = 32; s > 0; s >>= 1) {
        if (tid < s) red[tid] = fmaxf(red[tid], red[tid+s]);
        __syncthreads();
    }
    float mx = red[0]; __syncthreads();
    float ex = expf(l - mx);
    red[tid] = ex; __syncthreads();
    for (int s = 32; s > 0; s >>= 1) {
        if (tid < s) red[tid] += red[tid+s];
        __syncthreads();
    }
    float p = ex / red[0];
    sp[tid] = p;
    atomicAdd(&g_probsum[tid], p);
    __syncthreads();
    if (tid == 0) {
        // stable top-8: strict > keeps lowest index on ties (matches lax.top_k)
        for (int k = 0; k < Kn; k++) {
            float bv = -1.f; int bi = 0;
            for (int e = 0; e < En; e++) {
                float v = sp[e];
                if (v > bv) { bv = v; bi = e; }
            }
            g_topi[k*Tn + t] = bi;
            g_topv[k*Tn + t] = bv;
            sp[bi] = -1.f;
        }
    }
}

__global__ void hist_kernel() {
    __shared__ int cnt[En];
    int tid = threadIdx.x;
    if (tid < En) cnt[tid] = 0;
    __syncthreads();
    int a = blockIdx.x * CHSZ + tid;
    int e = g_topi[a];
    atomicAdd(&cnt[e], 1);
    __syncthreads();
    if (tid < En) g_chunkcnt[blockIdx.x*En + tid] = cnt[tid];
}

__global__ void scan_kernel() {
    int e = threadIdx.x;   // 64 threads
    int run = 0;
    for (int c = 0; c < NCHUNK; c++) {
        g_basecnt[c*En + e] = run;
        run += g_chunkcnt[c*En + e];
    }
    g_totcnt[e] = run;
    g_cnt[e] = run < Cn ? run : Cn;
}

__global__ void pos_kernel() {
    __shared__ int se[CHSZ];
    int tid = threadIdx.x;
    int a = blockIdx.x * CHSZ + tid;
    int e = g_topi[a];
    se[tid] = e;
    __syncthreads();
    int rank = 0;
    for (int j = 0; j < tid; j++) rank += (se[j] == e);
    int slot = g_basecnt[blockIdx.x*En + e] + rank;
    if (slot < Cn) {
        int t = a & (Tn - 1);          // a = k*T + t
        g_tok[e*Cn + slot] = t;
        g_wslot[e*Cn + slot] = g_topv[a];
    }
}

// ---------------- shared experts ----------------
__global__ __launch_bounds__(256) void shared_gu_kernel(
    const float* __restrict__ x,
    const float* __restrict__ swg, const float* __restrict__ swu)
{
    __shared__ float As[64*16];
    __shared__ float Bgs[16*64];
    __shared__ float Bus[16*64];
    __shared__ const float* Arows[64];
    int tid = threadIdx.x;
    int e = blockIdx.z;
    int m0 = blockIdx.y * 64, n0 = blockIdx.x * 64;
    if (tid < 64) Arows[tid] = x + (size_t)(m0 + tid) * Hn;
    __syncthreads();
    float accg[16] = {}, accu[16] = {};
    gemm2_core(Arows, swg + (size_t)e*Hn*F2n, swu + (size_t)e*Hn*F2n,
               F2n, Hn, n0, accg, accu, As, Bgs, Bus);
    int tx = tid & 15, ty = tid >> 4;
#pragma unroll
    for (int i = 0; i < 4; i++) {
        int m = m0 + ty*4 + i;
        float4 r;
        r.x = fmaxf(accg[i*4+0], 0.f) * accu[i*4+0];
        r.y = fmaxf(accg[i*4+1], 0.f) * accu[i*4+1];
        r.z = fmaxf(accg[i*4+2], 0.f) * accu[i*4+2];
        r.w = fmaxf(accg[i*4+3], 0.f) * accu[i*4+3];
        *(float4*)(g_hs + (size_t)m*(2*F2n) + (size_t)e*F2n + n0 + (tx<<2)) = r;
    }
}

// out = hs @ swd_flat : M=T, N=H, K=2F2 ; plain store (initializes out)
__global__ __launch_bounds__(256) void shared_down_kernel(
    const float* __restrict__ swd, float* __restrict__ out)
{
    __shared__ float As[64*16];
    __shared__ float Bs[16*64];
    __shared__ const float* Arows[64];
    int tid = threadIdx.x;
    int m0 = blockIdx.y * 64, n0 = blockIdx.x * 64;
    if (tid < 64) Arows[tid] = g_hs + (size_t)(m0 + tid) * (2*F2n);
    __syncthreads();
    float acc[16] = {};
    gemm1_core(Arows, swd, Hn, 2*F2n, n0, acc, As, Bs);
    int tx = tid & 15, ty = tid >> 4;
#pragma unroll
    for (int i = 0; i < 4; i++) {
        int m = m0 + ty*4 + i;
        float4 r = make_float4(acc[i*4+0], acc[i*4+1], acc[i*4+2], acc[i*4+3]);
        *(float4*)(out + (size_t)m*Hn + n0 + (tx<<2)) = r;
    }
}

// ---------------- expert FFN ----------------
__global__ __launch_bounds__(256) void expert_gu_kernel(
    const float* __restrict__ x,
    const float* __restrict__ wg, const float* __restrict__ wu)
{
    int e = blockIdx.z;
    int cnt = g_cnt[e];
    int m0 = blockIdx.y * 64;
    if (m0 >= cnt) return;
    int n0 = blockIdx.x * 64;
    __shared__ float As[64*16];
    __shared__ float Bgs[16*64];
    __shared__ float Bus[16*64];
    __shared__ const float* Arows[64];
    __shared__ float sw[64];
    int tid = threadIdx.x;
    if (tid < 64) {
        int m = m0 + tid;
        int tk = (m < cnt) ? g_tok[e*Cn + m] : 0;
        Arows[tid] = x + (size_t)tk * Hn;
        sw[tid] = (m < cnt) ? g_wslot[e*Cn + m] : 0.f;
    }
    __syncthreads();
    float accg[16] = {}, accu[16] = {};
    gemm2_core(Arows, wg + (size_t)e*Hn*Fn, wu + (size_t)e*Hn*Fn,
               Fn, Hn, n0, accg, accu, As, Bgs, Bus);
    int tx = tid & 15, ty = tid >> 4;
#pragma unroll
    for (int i = 0; i < 4; i++) {
        int row = m0 + ty*4 + i;
        if (row < cnt) {
            float w = sw[ty*4 + i];
            float4 r;
            r.x = fmaxf(accg[i*4+0], 0.f) * accu[i*4+0] * w;
            r.y = fmaxf(accg[i*4+1], 0.f) * accu[i*4+1] * w;
            r.z = fmaxf(accg[i*4+2], 0.f) * accu[i*4+2] * w;
            r.w = fmaxf(accg[i*4+3], 0.f) * accu[i*4+3] * w;
            *(float4*)(g_hbuf + ((size_t)e*Cn + row)*Fn + n0 + (tx<<2)) = r;
        }
    }
}

__global__ __launch_bounds__(256) void expert_down_kernel(
    const float* __restrict__ wd, float* __restrict__ out)
{
    int e = blockIdx.z;
    int cnt = g_cnt[e];
    int m0 = blockIdx.y * 64;
    if (m0 >= cnt) return;
    int n0 = blockIdx.x * 64;
    __shared__ float As[64*16];
    __shared__ float Bs[16*64];
    __shared__ const float* Arows[64];
    __shared__ int stok[64];
    int tid = threadIdx.x;
    if (tid < 64) {
        int m = m0 + tid;
        stok[tid] = (m < cnt) ? g_tok[e*Cn + m] : 0;
        Arows[tid] = g_hbuf + ((size_t)e*Cn + m) * Fn;  // rows >= cnt are zeros
    }
    __syncthreads();
    float acc[16] = {};
    gemm1_core(Arows, wd + (size_t)e*Fn*Hn, Hn, Fn, n0, acc, As, Bs);
    int tx = tid & 15, ty = tid >> 4;
#pragma unroll
    for (int i = 0; i < 4; i++) {
        int row = m0 + ty*4 + i;
        if (row < cnt) {
            float* op = out + (size_t)stok[ty*4+i]*Hn + n0 + (tx<<2);
            atomicAdd(op + 0, acc[i*4+0]);
            atomicAdd(op + 1, acc[i*4+1]);
            atomicAdd(op + 2, acc[i*4+2]);
            atomicAdd(op + 3, acc[i*4+3]);
        }
    }
}

__global__ void aux_kernel(float* __restrict__ out, int write_aux) {
    __shared__ float red[En];
    int e = threadIdx.x;  // 64 threads
    red[e] = (float)g_totcnt[e] * g_probsum[e];
    __syncthreads();
    for (int s = 32; s > 0; s >>= 1) {
        if (e < s) red[e] += red[e+s];
        __syncthreads();
    }
    if (e == 0 && write_aux) {
        // aux = E * sum_e (totcnt/(T*K)) * (probsum/T)
        out[(size_t)Tn*Hn] = (float)En * red[0] / ((float)Tn * (float)Kn * (float)Tn);
    }
}

// ---------------- launch ----------------
extern "C" void kernel_launch(void* const* d_in, const int* in_sizes, int n_in,
                              void* d_out, int out_size) {
    const float* x   = (const float*)d_in[0];
    const float* rw  = (const float*)d_in[1];
    const float* wg  = (const float*)d_in[2];
    const float* wu  = (const float*)d_in[3];
    const float* wd  = (const float*)d_in[4];
    const float* swg = (const float*)d_in[5];
    const float* swu = (const float*)d_in[6];
    const float* swd = (const float*)d_in[7];
    float* out = (float*)d_out;

    zero_kernel<<<1, 64>>>();
    logits_kernel<<<dim3(En/64, Tn/64), 256>>>(x, rw);
    router_post_kernel<<<Tn, 64>>>();
    hist_kernel<<<NCHUNK, CHSZ>>>();
    scan_kernel<<<1, En>>>();
    pos_kernel<<<NCHUNK, CHSZ>>>();

    shared_gu_kernel<<<dim3(F2n/64, Tn/64, 2), 256>>>(x, swg, swu);
    shared_down_kernel<<<dim3(Hn/64, Tn/64), 256>>>(swd, out);

    expert_gu_kernel<<<dim3(Fn/64, (Cn+63)/64, En), 256>>>(x, wg, wu);
    expert_down_kernel<<<dim3(Hn/64, (Cn+63)/64, En), 256>>>(wd, out);

    int write_aux = (out_size > Tn*Hn) ? 1 : 0;
    aux_kernel<<<1, En>>>(out, write_aux);
}